// round 15
// baseline (speedup 1.0000x reference)
#include <cuda_runtime.h>
#include <math.h>
#include <stdint.h>

// Problem constants
static const int CN = 32;    // batch
static const int CL = 512;   // nodes
static const int CP = 256;   // hyperedges
static const int CH = 8;     // heads
static const int CE = 128;   // emb per head
static const int CD = 1024;  // d_model

// -------- scratch (device globals; no allocation allowed) --------
// g_xh, g_he0, g_he, g_att2, g_w1t, g_w3t hold tf32-rounded bit patterns.
__device__ __align__(16) float    g_xh  [CN*CH*CL*CE];
__device__ __align__(16) float    g_he0 [CN*CH*CP*CE];
__device__ __align__(16) float    g_he  [CN*CH*CP*CE];
__device__ __align__(16) float    g_att2[CN*CH*CL*CP];
__device__ __align__(16) float    g_w1t [CE*CE];
__device__ __align__(16) float    g_w3t [CE*CE];
__device__ __align__(16) unsigned g_mbits[CN*CP*16];    // [n][p][l/32]
__device__ int   g_noedge[CN*CL];
__device__ float g_an[CN*CH*CL];
__device__ float g_s [CN*CH*CL];
__device__ float g_ae[CN*CH*CP];

__device__ __forceinline__ float gelu1(float x) {
    return 0.5f * x * (1.0f + erff(x * 0.7071067811865476f));
}
__device__ __forceinline__ unsigned f2tf(float x) {
    unsigned r; asm("cvt.rna.tf32.f32 %0, %1;" : "=r"(r) : "f"(x)); return r;
}
__device__ __forceinline__ void mma8(float* c, const unsigned* a, const unsigned* b) {
    asm volatile("mma.sync.aligned.m16n8k8.row.col.f32.tf32.tf32.f32 "
                 "{%0,%1,%2,%3},{%4,%5,%6,%7},{%8,%9},{%0,%1,%2,%3};"
                 : "+f"(c[0]), "+f"(c[1]), "+f"(c[2]), "+f"(c[3])
                 : "r"(a[0]), "r"(a[1]), "r"(a[2]), "r"(a[3]), "r"(b[0]), "r"(b[1]));
}
__device__ __forceinline__ void cpa16(void* dst, const void* src) {
    unsigned d = (unsigned)__cvta_generic_to_shared(dst);
    asm volatile("cp.async.cg.shared.global [%0], [%1], 16;" :: "r"(d), "l"(src));
}
#define CPA_COMMIT() asm volatile("cp.async.commit_group;" ::: "memory")
#define CPA_WAIT2()  asm volatile("cp.async.wait_group 2;" ::: "memory")
#define CPA_WAIT0()  asm volatile("cp.async.wait_group 0;" ::: "memory")

// -------- W pre-convert to tf32 bits --------
__global__ void __launch_bounds__(256) wcvt_k(const float* __restrict__ W1,
                                              const float* __restrict__ W3) {
    int i = blockIdx.x * 256 + threadIdx.x;
    g_w1t[i] = __uint_as_float(f2tf(W1[i]));
    g_w3t[i] = __uint_as_float(f2tf(W3[i]));
}

// -------- mask bit-pack --------
__global__ void __launch_bounds__(256) mbits_k(const float* __restrict__ adj) {
    __shared__ float sm[32 * 257];
    int l0 = blockIdx.x * 32, n = blockIdx.y;
    int t = threadIdx.x;   // = p
    for (int r = 0; r < 32; ++r)
        sm[r * 257 + t] = adj[((size_t)(n * CL) + l0 + r) * CP + t];
    __syncthreads();
    unsigned w = 0;
    #pragma unroll
    for (int j = 0; j < 32; ++j)
        if (sm[j * 257 + t] != 0.0f) w |= (1u << j);
    g_mbits[(n * CP + t) * 16 + (l0 >> 5)] = w;
}

// -------- node-attention fill (tf32 bits) + noedge flag --------
__global__ void __launch_bounds__(256) att2fill_k(const float* __restrict__ adj) {
    __shared__ float an_s[8];
    int l = blockIdx.x, n = blockIdx.y;
    int p = threadIdx.x;
    float mv = adj[((size_t)(n * CL) + l) * CP + p];
    int valid = (mv != 0.0f);
    if (p < 8) an_s[p] = g_an[(size_t)(n * 8 + p) * 512 + l];
    __syncthreads();
    unsigned sm[8];
    if (valid) {
        float u[8]; float mx = -1e30f;
        #pragma unroll
        for (int h = 0; h < 8; h++) {
            u[h] = an_s[h] + g_ae[(size_t)(n * 8 + h) * 256 + p];
            mx = fmaxf(mx, u[h]);
        }
        float s = 0.0f;
        #pragma unroll
        for (int h = 0; h < 8; h++) { u[h] = __expf(u[h] - mx); s += u[h]; }
        float inv = 1.0f / s;
        #pragma unroll
        for (int h = 0; h < 8; h++) sm[h] = f2tf(u[h] * inv);
    } else {
        #pragma unroll
        for (int h = 0; h < 8; h++) sm[h] = 0x3e000000u;   // tf32(0.125)
    }
    #pragma unroll
    for (int h = 0; h < 8; h++)
        g_att2[(((size_t)(n * 8 + h)) * 512 + l) * 256 + p] = __uint_as_float(sm[h]);
    int any = __syncthreads_or(valid);
    if (p == 0) g_noedge[n * CL + l] = !any;
}

// -------- unified tf32 MMA kernel: M-tile 64, 4-stage cp.async, 3 CTAs/SM ----
// MODE 0: A=x (cvt at frag), B=g_w1t, +b1, PERM -> g_xh(tf32); fused dots+softmax
// MODE 1: A=g_he0, B=g_w3t, +b3 -> g_he(tf32); fused gelu-dot -> g_ae
// MODE 2: per (n,h)x4: A=att1 synth from smem mbits/g_s, B=g_xh, gelu -> g_he0
// MODE 3: per (n,h)x8: A=g_att2, B=g_he, gelu/scatter -> out (fp32)
static const int NSTG = 4;
static const int MT   = 64;          // M-tile rows
static const int SA   = 20;          // A row stride (u32): 16 k + 4 pad
static const int ASZ  = MT * SA;     // 1280 words
static const int SB   = 136;         // B row stride (u32)
static const int BSZ  = 16 * SB;     // 2176 words
static const int MBW  = MT * 20;     // mbits cache words (MODE 2 only)
static const int SMEM_WORDS  = NSTG * (ASZ + BSZ) + 512 + 128 + 128 + 256 + 256;
static const int SMEM_BYTES  = SMEM_WORDS * 4;              // 60416 (modes 0/1/3)
static const int SMEM2_BYTES = (SMEM_WORDS + MBW) * 4;      // 65536 (mode 2)

template<int MODE>
__global__ void __launch_bounds__(256, 3) mma_k(const float* __restrict__ Aext,
                                                const float* __restrict__ bias,
                                                const float* __restrict__ wA,
                                                const float* __restrict__ wB,
                                                const float* __restrict__ xin,
                                                float* __restrict__ outx) {
    extern __shared__ unsigned dyns[];
    unsigned* As  = dyns;                     // NSTG*ASZ
    unsigned* Bs  = As + NSTG * ASZ;          // NSTG*BSZ
    unsigned* sS  = Bs + NSTG * BSZ;          // 512
    unsigned* sW2 = sS + 512;                 // 128
    unsigned* sW4 = sW2 + 128;                // 128
    float* sD1 = (float*)(sW4 + 128);         // 256
    float* sD2 = sD1 + 256;                   // 256
    unsigned* sMb = (unsigned*)(sD2 + 256);   // MODE 2 only: MT*20

    const int t = threadIdx.x;

    int nh = 0, m0 = 0, KT = 128, RS = 128;
    const float* Ag = Aext;
    const float* Bg = nullptr;
    if (MODE == 0) { m0 = blockIdx.x * MT; Bg = g_w1t; }
    if (MODE == 1) { m0 = blockIdx.x * MT; Ag = g_he0; Bg = g_w3t; }
    if (MODE == 2) { nh = blockIdx.x >> 2; m0 = (blockIdx.x & 3) * MT; KT = 512;
                     Bg = g_xh + (size_t)nh * 512 * 128; }
    if (MODE == 3) { nh = blockIdx.x >> 3; m0 = (blockIdx.x & 7) * MT; KT = 256; RS = 256;
                     Ag = g_att2 + (size_t)nh * 512 * 256;
                     Bg = g_he + (size_t)nh * 256 * 128; }
    const int NIT = KT / 16;

    if (MODE == 2) {
        sS[t]       = f2tf(g_s[(size_t)nh * 512 + t]);
        sS[t + 256] = f2tf(g_s[(size_t)nh * 512 + t + 256]);
        // preload this CTA's mbits slice (MT rows x 16 u32) into smem, stride 20
        {
            int r = t >> 2, q = t & 3;    // 256 chunks of 16B, one per thread
            cpa16(&sMb[r * 20 + q * 4],
                  g_mbits + ((size_t)((nh >> 3) * 256 + m0 + r)) * 16 + q * 4);
        }
        CPA_COMMIT();
        CPA_WAIT0();   // fully drained before the 3 pipeline groups are committed
    } else if (MODE == 0 || MODE == 1) {
        if (t < 128) {
            sS[t]  = __float_as_uint(bias[t]);
            sW2[t] = __float_as_uint(wA[t]);
            if (MODE == 0) sW4[t] = __float_as_uint(wB[t]);
        }
    }
    __syncthreads();   // sS + sMb visible before synth reads them

    const int lane = t & 31, wid = t >> 5;
    const int gq = lane >> 2, cq = lane & 3;
    const int wm = (wid & 1) * 32, wn = (wid >> 1) * 32;

    float acc[2][4][4];
    #pragma unroll
    for (int a = 0; a < 2; a++)
        #pragma unroll
        for (int b = 0; b < 4; b++)
            #pragma unroll
            for (int c = 0; c < 4; c++) acc[a][b][c] = 0.0f;

    auto issue = [&](int it) {
        if (it < NIT) {
            int k0 = it * 16, st = it & (NSTG - 1);
            #pragma unroll
            for (int rr = 0; rr < 2; rr++) {
                int i = t + 256 * rr;
                cpa16(&Bs[st * BSZ + (i >> 5) * SB + (i & 31) * 4],
                      Bg + (size_t)(k0 + (i >> 5)) * 128 + (i & 31) * 4);
            }
            if (MODE != 2) {
                // A tile: MT rows x 16 k = 256 chunks of 16B, one per thread
                int row = t >> 2, seg = t & 3;
                cpa16(&As[st * ASZ + row * SA + seg * 4],
                      Ag + (size_t)(m0 + row) * RS + k0 + seg * 4);
            }
        }
        CPA_COMMIT();
    };
    auto synth = [&](int it) {   // MODE 2 only: all smem, fully vectorized
        if (it < NIT && t < 128) {
            int k0 = it * 16, st = it & (NSTG - 1);
            int p = t & 63, kh = (t >> 6) * 8, sh = k0 & 16;
            unsigned pmb = sMb[p * 20 + (k0 >> 5)];
            uint4 s0 = *(const uint4*)&sS[k0 + kh];
            uint4 s1 = *(const uint4*)&sS[k0 + kh + 4];
            uint4 o0, o1;
            o0.x = ((pmb >> (sh + kh + 0)) & 1u) ? s0.x : 0x3e000000u;
            o0.y = ((pmb >> (sh + kh + 1)) & 1u) ? s0.y : 0x3e000000u;
            o0.z = ((pmb >> (sh + kh + 2)) & 1u) ? s0.z : 0x3e000000u;
            o0.w = ((pmb >> (sh + kh + 3)) & 1u) ? s0.w : 0x3e000000u;
            o1.x = ((pmb >> (sh + kh + 4)) & 1u) ? s1.x : 0x3e000000u;
            o1.y = ((pmb >> (sh + kh + 5)) & 1u) ? s1.y : 0x3e000000u;
            o1.z = ((pmb >> (sh + kh + 6)) & 1u) ? s1.z : 0x3e000000u;
            o1.w = ((pmb >> (sh + kh + 7)) & 1u) ? s1.w : 0x3e000000u;
            *(uint4*)&As[st * ASZ + p * SA + kh]     = o0;
            *(uint4*)&As[st * ASZ + p * SA + kh + 4] = o1;
        }
    };

    // prologue: stages 0..NSTG-2
    #pragma unroll
    for (int s = 0; s < NSTG - 1; s++) {
        issue(s);
        if (MODE == 2) synth(s);
    }

    for (int it = 0; it < NIT; ++it) {
        CPA_WAIT2();
        __syncthreads();
        const unsigned* Ab = &As[(it & (NSTG - 1)) * ASZ];
        const unsigned* Bb = &Bs[(it & (NSTG - 1)) * BSZ];
        #pragma unroll
        for (int ksc = 0; ksc < 2; ksc++) {
            int ks = ksc * 8;
            unsigned a[2][4], b[4][2];
            #pragma unroll
            for (int mi = 0; mi < 2; mi++) {
                int r0 = (wm + mi * 16 + gq) * SA + ks + cq;
                a[mi][0] = Ab[r0];
                a[mi][1] = Ab[r0 + 8 * SA];
                a[mi][2] = Ab[r0 + 4];
                a[mi][3] = Ab[r0 + 8 * SA + 4];
                if (MODE == 0) {
                    a[mi][0] = f2tf(__uint_as_float(a[mi][0]));
                    a[mi][1] = f2tf(__uint_as_float(a[mi][1]));
                    a[mi][2] = f2tf(__uint_as_float(a[mi][2]));
                    a[mi][3] = f2tf(__uint_as_float(a[mi][3]));
                }
            }
            #pragma unroll
            for (int ni = 0; ni < 4; ni++) {
                int o = (ks + cq) * SB + wn + ni * 8 + gq;
                b[ni][0] = Bb[o];
                b[ni][1] = Bb[o + 4 * SB];
            }
            #pragma unroll
            for (int mi = 0; mi < 2; mi++)
                #pragma unroll
                for (int ni = 0; ni < 4; ni++)
                    mma8(acc[mi][ni], a[mi], b[ni]);
        }
        issue(it + NSTG - 1);
        if (MODE == 2) synth(it + NSTG - 1);
    }

    // ---------------- epilogue ----------------
    float dA[4], dB[4];
    #pragma unroll
    for (int i = 0; i < 4; i++) { dA[i] = 0.0f; dB[i] = 0.0f; }

    #pragma unroll
    for (int mi = 0; mi < 2; mi++) {
        #pragma unroll
        for (int half = 0; half < 2; half++) {
            int rl = wm + mi * 16 + gq + half * 8;   // 0..63
            int di = mi * 2 + half;
            size_t base = 0;
            int noe = 0;
            if (MODE == 0) {
                int rowg = m0 + rl;
                int n = rowg >> 12, rem = rowg & 4095;
                int l = rem >> 3, h = rem & 7;
                base = ((size_t)((n * 8 + h) * 512 + l)) * 128;
            } else if (MODE == 1) {
                base = (size_t)(m0 + rl) * 128;
            } else if (MODE == 2) {
                base = ((size_t)(nh * 256 + m0 + rl)) * 128;
            } else {
                int l = m0 + rl;
                int n = nh >> 3, h = nh & 7;
                noe = g_noedge[n * CL + l];
                base = ((size_t)(n * CL + l)) * 1024 + h * 128;
            }
            #pragma unroll
            for (int ni = 0; ni < 4; ni++) {
                int col = wn + ni * 8 + 2 * cq;
                float v0 = acc[mi][ni][half * 2 + 0];
                float v1 = acc[mi][ni][half * 2 + 1];
                if (MODE == 0 || MODE == 1) {
                    v0 += __uint_as_float(sS[col]);
                    v1 += __uint_as_float(sS[col + 1]);
                    float g0 = gelu1(v0), g1 = gelu1(v1);
                    dA[di] += g0 * __uint_as_float(sW2[col]) + g1 * __uint_as_float(sW2[col + 1]);
                    if (MODE == 0)
                        dB[di] += g0 * __uint_as_float(sW4[col]) + g1 * __uint_as_float(sW4[col + 1]);
                    float* dst = (MODE == 0) ? g_xh : g_he;
                    *(float2*)(dst + base + col) =
                        make_float2(__uint_as_float(f2tf(v0)), __uint_as_float(f2tf(v1)));
                } else if (MODE == 2) {
                    *(float2*)(g_he0 + base + col) =
                        make_float2(__uint_as_float(f2tf(gelu1(v0))),
                                    __uint_as_float(f2tf(gelu1(v1))));
                } else {
                    float2 r;
                    if (noe) r = *(const float2*)(xin + base + col);
                    else     r = make_float2(gelu1(v0), gelu1(v1));
                    *(float2*)(outx + base + col) = r;
                }
            }
        }
    }

    if (MODE == 0 || MODE == 1) {
        #pragma unroll
        for (int i = 0; i < 4; i++) {
            dA[i] += __shfl_xor_sync(0xffffffffu, dA[i], 1);
            dA[i] += __shfl_xor_sync(0xffffffffu, dA[i], 2);
            if (MODE == 0) {
                dB[i] += __shfl_xor_sync(0xffffffffu, dB[i], 1);
                dB[i] += __shfl_xor_sync(0xffffffffu, dB[i], 2);
            }
        }
        if (cq == 0) {
            #pragma unroll
            for (int i = 0; i < 4; i++) {
                int rl = wm + (i >> 1) * 16 + gq + 8 * (i & 1);
                sD1[(wid >> 1) * 64 + rl] = dA[i];
                if (MODE == 0) sD2[(wid >> 1) * 64 + rl] = dB[i];
            }
        }
        __syncthreads();
        if (t < 64) {   // warps 0..1 fully active
            float d1 = sD1[t] + sD1[64 + t] + sD1[128 + t] + sD1[192 + t];
            if (MODE == 1) {
                g_ae[m0 + t] = d1;
            } else {
                float d2 = sD2[t] + sD2[64 + t] + sD2[128 + t] + sD2[192 + t];
                int rowg = m0 + t;
                int n = rowg >> 12, rem = rowg & 4095;
                int l = rem >> 3, h = rem & 7;
                g_an[(size_t)(n * 8 + h) * 512 + l] = d2;
                float mx = d1;
                mx = fmaxf(mx, __shfl_xor_sync(0xffffffffu, mx, 1));
                mx = fmaxf(mx, __shfl_xor_sync(0xffffffffu, mx, 2));
                mx = fmaxf(mx, __shfl_xor_sync(0xffffffffu, mx, 4));
                float e = __expf(d1 - mx);
                float se = e;
                se += __shfl_xor_sync(0xffffffffu, se, 1);
                se += __shfl_xor_sync(0xffffffffu, se, 2);
                se += __shfl_xor_sync(0xffffffffu, se, 4);
                g_s[(size_t)(n * 8 + h) * 512 + l] = e / se;
            }
        }
    }
}

extern "C" void kernel_launch(void* const* d_in, const int* in_sizes, int n_in,
                              void* d_out, int out_size) {
    const float* x   = (const float*)d_in[0];
    const float* adj = (const float*)d_in[1];
    const float* W1  = (const float*)d_in[2];
    const float* b1  = (const float*)d_in[3];
    const float* W2  = (const float*)d_in[4];
    const float* W3  = (const float*)d_in[6];
    const float* b3  = (const float*)d_in[7];
    const float* W4  = (const float*)d_in[8];
    float* out = (float*)d_out;
    (void)in_sizes; (void)n_in; (void)out_size;

    cudaFuncSetAttribute(mma_k<0>, cudaFuncAttributeMaxDynamicSharedMemorySize, SMEM_BYTES);
    cudaFuncSetAttribute(mma_k<1>, cudaFuncAttributeMaxDynamicSharedMemorySize, SMEM_BYTES);
    cudaFuncSetAttribute(mma_k<2>, cudaFuncAttributeMaxDynamicSharedMemorySize, SMEM2_BYTES);
    cudaFuncSetAttribute(mma_k<3>, cudaFuncAttributeMaxDynamicSharedMemorySize, SMEM_BYTES);

    wcvt_k<<<64, 256>>>(W1, W3);
    mbits_k<<<dim3(CL / 32, CN), 256>>>(adj);
    mma_k<0><<<(CN * CL * CH) / MT, 256, SMEM_BYTES>>>(x, b1, W2, W4 + CE, nullptr, nullptr);
    mma_k<2><<<CN * CH * 4, 256, SMEM2_BYTES>>>(nullptr, nullptr, nullptr, nullptr, nullptr, nullptr);
    mma_k<1><<<(CN * CH * CP) / MT, 256, SMEM_BYTES>>>(nullptr, b3, W4, nullptr, nullptr, nullptr);
    att2fill_k<<<dim3(CL, CN), 256>>>(adj);
    mma_k<3><<<CN * CH * 8, 256, SMEM_BYTES>>>(nullptr, nullptr, nullptr, nullptr, x, out);
}

// round 16
// speedup vs baseline: 1.0154x; 1.0154x over previous
#include <cuda_runtime.h>
#include <math.h>
#include <stdint.h>

// Problem constants
static const int CN = 32;    // batch
static const int CL = 512;   // nodes
static const int CP = 256;   // hyperedges
static const int CH = 8;     // heads
static const int CE = 128;   // emb per head
static const int CD = 1024;  // d_model

// -------- scratch (device globals; no allocation allowed) --------
// g_xh, g_he0, g_he, g_att2, g_w1t, g_w3t hold tf32-rounded bit patterns.
__device__ __align__(16) float    g_xh  [CN*CH*CL*CE];
__device__ __align__(16) float    g_he0 [CN*CH*CP*CE];
__device__ __align__(16) float    g_he  [CN*CH*CP*CE];
__device__ __align__(16) float    g_att2[CN*CH*CL*CP];
__device__ __align__(16) float    g_w1t [CE*CE];
__device__ __align__(16) float    g_w3t [CE*CE];
__device__ __align__(16) unsigned g_mbits[CN*CP*16];    // [n][p][l/32]
__device__ int   g_noedge[CN*CL];
__device__ float g_an[CN*CH*CL];
__device__ float g_s [CN*CH*CL];
__device__ float g_ae[CN*CH*CP];

__device__ __forceinline__ float gelu1(float x) {
    return 0.5f * x * (1.0f + erff(x * 0.7071067811865476f));
}
__device__ __forceinline__ unsigned f2tf(float x) {
    unsigned r; asm("cvt.rna.tf32.f32 %0, %1;" : "=r"(r) : "f"(x)); return r;
}
__device__ __forceinline__ void mma8(float* c, const unsigned* a, const unsigned* b) {
    asm volatile("mma.sync.aligned.m16n8k8.row.col.f32.tf32.tf32.f32 "
                 "{%0,%1,%2,%3},{%4,%5,%6,%7},{%8,%9},{%0,%1,%2,%3};"
                 : "+f"(c[0]), "+f"(c[1]), "+f"(c[2]), "+f"(c[3])
                 : "r"(a[0]), "r"(a[1]), "r"(a[2]), "r"(a[3]), "r"(b[0]), "r"(b[1]));
}
__device__ __forceinline__ void cpa16(void* dst, const void* src) {
    unsigned d = (unsigned)__cvta_generic_to_shared(dst);
    asm volatile("cp.async.cg.shared.global [%0], [%1], 16;" :: "r"(d), "l"(src));
}
#define CPA_COMMIT() asm volatile("cp.async.commit_group;" ::: "memory")
#define CPA_WAIT2()  asm volatile("cp.async.wait_group 2;" ::: "memory")
#define CPA_WAIT0()  asm volatile("cp.async.wait_group 0;" ::: "memory")

// -------- W pre-convert to tf32 bits --------
__global__ void __launch_bounds__(256) wcvt_k(const float* __restrict__ W1,
                                              const float* __restrict__ W3) {
    int i = blockIdx.x * 256 + threadIdx.x;
    g_w1t[i] = __uint_as_float(f2tf(W1[i]));
    g_w3t[i] = __uint_as_float(f2tf(W3[i]));
}

// -------- mask bit-pack --------
__global__ void __launch_bounds__(256) mbits_k(const float* __restrict__ adj) {
    __shared__ float sm[32 * 257];
    int l0 = blockIdx.x * 32, n = blockIdx.y;
    int t = threadIdx.x;   // = p
    for (int r = 0; r < 32; ++r)
        sm[r * 257 + t] = adj[((size_t)(n * CL) + l0 + r) * CP + t];
    __syncthreads();
    unsigned w = 0;
    #pragma unroll
    for (int j = 0; j < 32; ++j)
        if (sm[j * 257 + t] != 0.0f) w |= (1u << j);
    g_mbits[(n * CP + t) * 16 + (l0 >> 5)] = w;
}

// -------- node-attention fill (tf32 bits) + noedge flag --------
__global__ void __launch_bounds__(256) att2fill_k(const float* __restrict__ adj) {
    __shared__ float an_s[8];
    int l = blockIdx.x, n = blockIdx.y;
    int p = threadIdx.x;
    float mv = adj[((size_t)(n * CL) + l) * CP + p];
    int valid = (mv != 0.0f);
    if (p < 8) an_s[p] = g_an[(size_t)(n * 8 + p) * 512 + l];
    __syncthreads();
    unsigned sm[8];
    if (valid) {
        float u[8]; float mx = -1e30f;
        #pragma unroll
        for (int h = 0; h < 8; h++) {
            u[h] = an_s[h] + g_ae[(size_t)(n * 8 + h) * 256 + p];
            mx = fmaxf(mx, u[h]);
        }
        float s = 0.0f;
        #pragma unroll
        for (int h = 0; h < 8; h++) { u[h] = __expf(u[h] - mx); s += u[h]; }
        float inv = 1.0f / s;
        #pragma unroll
        for (int h = 0; h < 8; h++) sm[h] = f2tf(u[h] * inv);
    } else {
        #pragma unroll
        for (int h = 0; h < 8; h++) sm[h] = 0x3e000000u;   // tf32(0.125)
    }
    #pragma unroll
    for (int h = 0; h < 8; h++)
        g_att2[(((size_t)(n * 8 + h)) * 512 + l) * 256 + p] = __uint_as_float(sm[h]);
    int any = __syncthreads_or(valid);
    if (p == 0) g_noedge[n * CL + l] = !any;
}

// -------- unified tf32 MMA kernel: M-tile 64, 4-stage cp.async, 3 CTAs/SM ----
// MODE 0: A=x (cvt at frag), B=g_w1t, +b1, PERM -> g_xh(tf32); fused dots+softmax
// MODE 1: A=g_he0, B=g_w3t, +b3 -> g_he(tf32); fused gelu-dot -> g_ae
// MODE 2: per (n,h)x4: A=att1 synth in quad layout, B=g_xh, gelu -> g_he0
// MODE 3: per (n,h)x8: A=g_att2, B=g_he, gelu/scatter -> out (fp32)
// MODE 2 A layout: 8 blocks (m16 0..3 x ksc 0..1) of 136 words; block holds 32
// rotated quads; quad of thread (gq,cq) at slot (gq*4+((cq+gq)&3))*4 contains
// words {(row g, k c), (g+8, c), (g, c+4), (g+8, c+4)} — one LDS.128/fragment.
static const int NSTG = 4;
static const int MT   = 64;          // M-tile rows
static const int SA   = 20;          // A row stride (u32): 16 k + 4 pad (modes 0/1/3)
static const int ASZ  = MT * SA;     // 1280 words (mode 2 uses first 8*136=1088)
static const int SB   = 136;         // B row stride (u32)
static const int BSZ  = 16 * SB;     // 2176 words
static const int MBW  = MT * 20;     // mbits cache words (MODE 2 only)
static const int SMEM_WORDS  = NSTG * (ASZ + BSZ) + 512 + 128 + 128 + 256 + 256;
static const int SMEM_BYTES  = SMEM_WORDS * 4;              // 60416 (modes 0/1/3)
static const int SMEM2_BYTES = (SMEM_WORDS + MBW) * 4;      // 65536 (mode 2)

template<int MODE>
__global__ void __launch_bounds__(256, 3) mma_k(const float* __restrict__ Aext,
                                                const float* __restrict__ bias,
                                                const float* __restrict__ wA,
                                                const float* __restrict__ wB,
                                                const float* __restrict__ xin,
                                                float* __restrict__ outx) {
    extern __shared__ unsigned dyns[];
    unsigned* As  = dyns;                     // NSTG*ASZ
    unsigned* Bs  = As + NSTG * ASZ;          // NSTG*BSZ
    unsigned* sS  = Bs + NSTG * BSZ;          // 512
    unsigned* sW2 = sS + 512;                 // 128
    unsigned* sW4 = sW2 + 128;                // 128
    float* sD1 = (float*)(sW4 + 128);         // 256
    float* sD2 = sD1 + 256;                   // 256
    unsigned* sMb = (unsigned*)(sD2 + 256);   // MODE 2 only: MT*20

    const int t = threadIdx.x;

    int nh = 0, m0 = 0, KT = 128, RS = 128;
    const float* Ag = Aext;
    const float* Bg = nullptr;
    if (MODE == 0) { m0 = blockIdx.x * MT; Bg = g_w1t; }
    if (MODE == 1) { m0 = blockIdx.x * MT; Ag = g_he0; Bg = g_w3t; }
    if (MODE == 2) { nh = blockIdx.x >> 2; m0 = (blockIdx.x & 3) * MT; KT = 512;
                     Bg = g_xh + (size_t)nh * 512 * 128; }
    if (MODE == 3) { nh = blockIdx.x >> 3; m0 = (blockIdx.x & 7) * MT; KT = 256; RS = 256;
                     Ag = g_att2 + (size_t)nh * 512 * 256;
                     Bg = g_he + (size_t)nh * 256 * 128; }
    const int NIT = KT / 16;

    if (MODE == 2) {
        sS[t]       = f2tf(g_s[(size_t)nh * 512 + t]);
        sS[t + 256] = f2tf(g_s[(size_t)nh * 512 + t + 256]);
        // preload this CTA's mbits slice (MT rows x 16 u32) into smem, stride 20
        {
            int r = t >> 2, q = t & 3;    // 256 chunks of 16B, one per thread
            cpa16(&sMb[r * 20 + q * 4],
                  g_mbits + ((size_t)((nh >> 3) * 256 + m0 + r)) * 16 + q * 4);
        }
        CPA_COMMIT();
        CPA_WAIT0();   // fully drained before the 3 pipeline groups are committed
    } else if (MODE == 0 || MODE == 1) {
        if (t < 128) {
            sS[t]  = __float_as_uint(bias[t]);
            sW2[t] = __float_as_uint(wA[t]);
            if (MODE == 0) sW4[t] = __float_as_uint(wB[t]);
        }
    }
    __syncthreads();   // sS + sMb visible before synth reads them

    const int lane = t & 31, wid = t >> 5;
    const int gq = lane >> 2, cq = lane & 3;
    const int wm = (wid & 1) * 32, wn = (wid >> 1) * 32;
    const int slotA = (gq * 4 + ((cq + gq) & 3)) * 4;   // MODE 2 quad slot
    const int m16w = wm >> 4;                            // 0 or 2

    float acc[2][4][4];
    #pragma unroll
    for (int a = 0; a < 2; a++)
        #pragma unroll
        for (int b = 0; b < 4; b++)
            #pragma unroll
            for (int c = 0; c < 4; c++) acc[a][b][c] = 0.0f;

    auto issue = [&](int it) {
        if (it < NIT) {
            int k0 = it * 16, st = it & (NSTG - 1);
            #pragma unroll
            for (int rr = 0; rr < 2; rr++) {
                int i = t + 256 * rr;
                cpa16(&Bs[st * BSZ + (i >> 5) * SB + (i & 31) * 4],
                      Bg + (size_t)(k0 + (i >> 5)) * 128 + (i & 31) * 4);
            }
            if (MODE != 2) {
                // A tile: MT rows x 16 k = 256 chunks of 16B, one per thread
                int row = t >> 2, seg = t & 3;
                cpa16(&As[st * ASZ + row * SA + seg * 4],
                      Ag + (size_t)(m0 + row) * RS + k0 + seg * 4);
            }
        }
        CPA_COMMIT();
    };
    auto synth = [&](int it) {   // MODE 2 only: build one rotated quad per thread
        if (it < NIT) {
            int k0 = it * 16, st = it & (NSTG - 1);
            int b = t >> 5;               // block 0..7: m16 = b>>1, ksc = b&1
            int g = (t >> 2) & 7, c = t & 3;
            int r0 = (b >> 1) * 16 + g;   // row, row+8
            int kc = (b & 1) * 8 + c;     // k within chunk, +4
            int sh = k0 & 16;
            unsigned mb0 = sMb[r0 * 20 + (k0 >> 5)];
            unsigned mb1 = sMb[(r0 + 8) * 20 + (k0 >> 5)];
            unsigned sc  = sS[k0 + kc];
            unsigned sc4 = sS[k0 + kc + 4];
            uint4 q;
            q.x = ((mb0 >> (sh + kc)) & 1u)     ? sc  : 0x3e000000u;
            q.y = ((mb1 >> (sh + kc)) & 1u)     ? sc  : 0x3e000000u;
            q.z = ((mb0 >> (sh + kc + 4)) & 1u) ? sc4 : 0x3e000000u;
            q.w = ((mb1 >> (sh + kc + 4)) & 1u) ? sc4 : 0x3e000000u;
            int slot = (g * 4 + ((c + g) & 3)) * 4;
            *(uint4*)&As[st * ASZ + b * 136 + slot] = q;
        }
    };

    // prologue: stages 0..NSTG-2
    #pragma unroll
    for (int s = 0; s < NSTG - 1; s++) {
        issue(s);
        if (MODE == 2) synth(s);
    }

    for (int it = 0; it < NIT; ++it) {
        CPA_WAIT2();
        __syncthreads();
        const unsigned* Ab = &As[(it & (NSTG - 1)) * ASZ];
        const unsigned* Bb = &Bs[(it & (NSTG - 1)) * BSZ];
        #pragma unroll
        for (int ksc = 0; ksc < 2; ksc++) {
            int ks = ksc * 8;
            unsigned a[2][4], b[4][2];
            #pragma unroll
            for (int mi = 0; mi < 2; mi++) {
                if (MODE == 2) {
                    uint4 v = *(const uint4*)&Ab[((m16w + mi) * 2 + ksc) * 136 + slotA];
                    a[mi][0] = v.x; a[mi][1] = v.y; a[mi][2] = v.z; a[mi][3] = v.w;
                } else {
                    int r0 = (wm + mi * 16 + gq) * SA + ks + cq;
                    a[mi][0] = Ab[r0];
                    a[mi][1] = Ab[r0 + 8 * SA];
                    a[mi][2] = Ab[r0 + 4];
                    a[mi][3] = Ab[r0 + 8 * SA + 4];
                    if (MODE == 0) {
                        a[mi][0] = f2tf(__uint_as_float(a[mi][0]));
                        a[mi][1] = f2tf(__uint_as_float(a[mi][1]));
                        a[mi][2] = f2tf(__uint_as_float(a[mi][2]));
                        a[mi][3] = f2tf(__uint_as_float(a[mi][3]));
                    }
                }
            }
            #pragma unroll
            for (int ni = 0; ni < 4; ni++) {
                int o = (ks + cq) * SB + wn + ni * 8 + gq;
                b[ni][0] = Bb[o];
                b[ni][1] = Bb[o + 4 * SB];
            }
            #pragma unroll
            for (int mi = 0; mi < 2; mi++)
                #pragma unroll
                for (int ni = 0; ni < 4; ni++)
                    mma8(acc[mi][ni], a[mi], b[ni]);
        }
        issue(it + NSTG - 1);
        if (MODE == 2) synth(it + NSTG - 1);
    }

    // ---------------- epilogue ----------------
    float dA[4], dB[4];
    #pragma unroll
    for (int i = 0; i < 4; i++) { dA[i] = 0.0f; dB[i] = 0.0f; }

    #pragma unroll
    for (int mi = 0; mi < 2; mi++) {
        #pragma unroll
        for (int half = 0; half < 2; half++) {
            int rl = wm + mi * 16 + gq + half * 8;   // 0..63
            int di = mi * 2 + half;
            size_t base = 0;
            int noe = 0;
            if (MODE == 0) {
                int rowg = m0 + rl;
                int n = rowg >> 12, rem = rowg & 4095;
                int l = rem >> 3, h = rem & 7;
                base = ((size_t)((n * 8 + h) * 512 + l)) * 128;
            } else if (MODE == 1) {
                base = (size_t)(m0 + rl) * 128;
            } else if (MODE == 2) {
                base = ((size_t)(nh * 256 + m0 + rl)) * 128;
            } else {
                int l = m0 + rl;
                int n = nh >> 3, h = nh & 7;
                noe = g_noedge[n * CL + l];
                base = ((size_t)(n * CL + l)) * 1024 + h * 128;
            }
            #pragma unroll
            for (int ni = 0; ni < 4; ni++) {
                int col = wn + ni * 8 + 2 * cq;
                float v0 = acc[mi][ni][half * 2 + 0];
                float v1 = acc[mi][ni][half * 2 + 1];
                if (MODE == 0 || MODE == 1) {
                    v0 += __uint_as_float(sS[col]);
                    v1 += __uint_as_float(sS[col + 1]);
                    float g0 = gelu1(v0), g1 = gelu1(v1);
                    dA[di] += g0 * __uint_as_float(sW2[col]) + g1 * __uint_as_float(sW2[col + 1]);
                    if (MODE == 0)
                        dB[di] += g0 * __uint_as_float(sW4[col]) + g1 * __uint_as_float(sW4[col + 1]);
                    float* dst = (MODE == 0) ? g_xh : g_he;
                    *(float2*)(dst + base + col) =
                        make_float2(__uint_as_float(f2tf(v0)), __uint_as_float(f2tf(v1)));
                } else if (MODE == 2) {
                    *(float2*)(g_he0 + base + col) =
                        make_float2(__uint_as_float(f2tf(gelu1(v0))),
                                    __uint_as_float(f2tf(gelu1(v1))));
                } else {
                    float2 r;
                    if (noe) r = *(const float2*)(xin + base + col);
                    else     r = make_float2(gelu1(v0), gelu1(v1));
                    *(float2*)(outx + base + col) = r;
                }
            }
        }
    }

    if (MODE == 0 || MODE == 1) {
        #pragma unroll
        for (int i = 0; i < 4; i++) {
            dA[i] += __shfl_xor_sync(0xffffffffu, dA[i], 1);
            dA[i] += __shfl_xor_sync(0xffffffffu, dA[i], 2);
            if (MODE == 0) {
                dB[i] += __shfl_xor_sync(0xffffffffu, dB[i], 1);
                dB[i] += __shfl_xor_sync(0xffffffffu, dB[i], 2);
            }
        }
        if (cq == 0) {
            #pragma unroll
            for (int i = 0; i < 4; i++) {
                int rl = wm + (i >> 1) * 16 + gq + 8 * (i & 1);
                sD1[(wid >> 1) * 64 + rl] = dA[i];
                if (MODE == 0) sD2[(wid >> 1) * 64 + rl] = dB[i];
            }
        }
        __syncthreads();
        if (t < 64) {   // warps 0..1 fully active
            float d1 = sD1[t] + sD1[64 + t] + sD1[128 + t] + sD1[192 + t];
            if (MODE == 1) {
                g_ae[m0 + t] = d1;
            } else {
                float d2 = sD2[t] + sD2[64 + t] + sD2[128 + t] + sD2[192 + t];
                int rowg = m0 + t;
                int n = rowg >> 12, rem = rowg & 4095;
                int l = rem >> 3, h = rem & 7;
                g_an[(size_t)(n * 8 + h) * 512 + l] = d2;
                float mx = d1;
                mx = fmaxf(mx, __shfl_xor_sync(0xffffffffu, mx, 1));
                mx = fmaxf(mx, __shfl_xor_sync(0xffffffffu, mx, 2));
                mx = fmaxf(mx, __shfl_xor_sync(0xffffffffu, mx, 4));
                float e = __expf(d1 - mx);
                float se = e;
                se += __shfl_xor_sync(0xffffffffu, se, 1);
                se += __shfl_xor_sync(0xffffffffu, se, 2);
                se += __shfl_xor_sync(0xffffffffu, se, 4);
                g_s[(size_t)(n * 8 + h) * 512 + l] = e / se;
            }
        }
    }
}

extern "C" void kernel_launch(void* const* d_in, const int* in_sizes, int n_in,
                              void* d_out, int out_size) {
    const float* x   = (const float*)d_in[0];
    const float* adj = (const float*)d_in[1];
    const float* W1  = (const float*)d_in[2];
    const float* b1  = (const float*)d_in[3];
    const float* W2  = (const float*)d_in[4];
    const float* W3  = (const float*)d_in[6];
    const float* b3  = (const float*)d_in[7];
    const float* W4  = (const float*)d_in[8];
    float* out = (float*)d_out;
    (void)in_sizes; (void)n_in; (void)out_size;

    cudaFuncSetAttribute(mma_k<0>, cudaFuncAttributeMaxDynamicSharedMemorySize, SMEM_BYTES);
    cudaFuncSetAttribute(mma_k<1>, cudaFuncAttributeMaxDynamicSharedMemorySize, SMEM_BYTES);
    cudaFuncSetAttribute(mma_k<2>, cudaFuncAttributeMaxDynamicSharedMemorySize, SMEM2_BYTES);
    cudaFuncSetAttribute(mma_k<3>, cudaFuncAttributeMaxDynamicSharedMemorySize, SMEM_BYTES);

    wcvt_k<<<64, 256>>>(W1, W3);
    mbits_k<<<dim3(CL / 32, CN), 256>>>(adj);
    mma_k<0><<<(CN * CL * CH) / MT, 256, SMEM_BYTES>>>(x, b1, W2, W4 + CE, nullptr, nullptr);
    mma_k<2><<<CN * CH * 4, 256, SMEM2_BYTES>>>(nullptr, nullptr, nullptr, nullptr, nullptr, nullptr);
    mma_k<1><<<(CN * CH * CP) / MT, 256, SMEM_BYTES>>>(nullptr, b3, W4, nullptr, nullptr, nullptr);
    att2fill_k<<<dim3(CL, CN), 256>>>(adj);
    mma_k<3><<<CN * CH * 8, 256, SMEM_BYTES>>>(nullptr, nullptr, nullptr, nullptr, x, out);
}

// round 17
// speedup vs baseline: 1.0159x; 1.0005x over previous
#include <cuda_runtime.h>
#include <math.h>
#include <stdint.h>

// Problem constants
static const int CN = 32;    // batch
static const int CL = 512;   // nodes
static const int CP = 256;   // hyperedges
static const int CH = 8;     // heads
static const int CE = 128;   // emb per head
static const int CD = 1024;  // d_model

// -------- scratch (device globals; no allocation allowed) --------
// g_xh, g_he, g_att2, g_w1t, g_w3t hold tf32-rounded bit patterns.
__device__ __align__(16) float    g_xh  [CN*CH*CL*CE];
__device__ __align__(16) float    g_he  [CN*CH*CP*CE];
__device__ __align__(16) float    g_att2[CN*CH*CL*CP];
__device__ __align__(16) float    g_w1t [CE*CE];
__device__ __align__(16) float    g_w3t [CE*CE];
__device__ __align__(16) unsigned g_mbits[CN*CP*16];    // [n][p][l/32]
__device__ int   g_noedge[CN*CL];
__device__ float g_an[CN*CH*CL];
__device__ float g_s [CN*CH*CL];
__device__ float g_ae[CN*CH*CP];

__device__ __forceinline__ float gelu1(float x) {
    return 0.5f * x * (1.0f + erff(x * 0.7071067811865476f));
}
__device__ __forceinline__ unsigned f2tf(float x) {
    unsigned r; asm("cvt.rna.tf32.f32 %0, %1;" : "=r"(r) : "f"(x)); return r;
}
__device__ __forceinline__ void mma8(float* c, const unsigned* a, const unsigned* b) {
    asm volatile("mma.sync.aligned.m16n8k8.row.col.f32.tf32.tf32.f32 "
                 "{%0,%1,%2,%3},{%4,%5,%6,%7},{%8,%9},{%0,%1,%2,%3};"
                 : "+f"(c[0]), "+f"(c[1]), "+f"(c[2]), "+f"(c[3])
                 : "r"(a[0]), "r"(a[1]), "r"(a[2]), "r"(a[3]), "r"(b[0]), "r"(b[1]));
}
__device__ __forceinline__ void cpa16(void* dst, const void* src) {
    unsigned d = (unsigned)__cvta_generic_to_shared(dst);
    asm volatile("cp.async.cg.shared.global [%0], [%1], 16;" :: "r"(d), "l"(src));
}
#define CPA_COMMIT() asm volatile("cp.async.commit_group;" ::: "memory")
#define CPA_WAIT2()  asm volatile("cp.async.wait_group 2;" ::: "memory")
#define CPA_WAIT0()  asm volatile("cp.async.wait_group 0;" ::: "memory")

// -------- W pre-convert to tf32 bits --------
__global__ void __launch_bounds__(256) wcvt_k(const float* __restrict__ W1,
                                              const float* __restrict__ W3) {
    int i = blockIdx.x * 256 + threadIdx.x;
    g_w1t[i] = __uint_as_float(f2tf(W1[i]));
    g_w3t[i] = __uint_as_float(f2tf(W3[i]));
}

// -------- mask bit-pack --------
__global__ void __launch_bounds__(256) mbits_k(const float* __restrict__ adj) {
    __shared__ float sm[32 * 257];
    int l0 = blockIdx.x * 32, n = blockIdx.y;
    int t = threadIdx.x;   // = p
    for (int r = 0; r < 32; ++r)
        sm[r * 257 + t] = adj[((size_t)(n * CL) + l0 + r) * CP + t];
    __syncthreads();
    unsigned w = 0;
    #pragma unroll
    for (int j = 0; j < 32; ++j)
        if (sm[j * 257 + t] != 0.0f) w |= (1u << j);
    g_mbits[(n * CP + t) * 16 + (l0 >> 5)] = w;
}

// -------- node-attention fill (tf32 bits) + noedge flag --------
__global__ void __launch_bounds__(256) att2fill_k(const float* __restrict__ adj) {
    __shared__ float an_s[8];
    int l = blockIdx.x, n = blockIdx.y;
    int p = threadIdx.x;
    float mv = adj[((size_t)(n * CL) + l) * CP + p];
    int valid = (mv != 0.0f);
    if (p < 8) an_s[p] = g_an[(size_t)(n * 8 + p) * 512 + l];
    __syncthreads();
    unsigned sm[8];
    if (valid) {
        float u[8]; float mx = -1e30f;
        #pragma unroll
        for (int h = 0; h < 8; h++) {
            u[h] = an_s[h] + g_ae[(size_t)(n * 8 + h) * 256 + p];
            mx = fmaxf(mx, u[h]);
        }
        float s = 0.0f;
        #pragma unroll
        for (int h = 0; h < 8; h++) { u[h] = __expf(u[h] - mx); s += u[h]; }
        float inv = 1.0f / s;
        #pragma unroll
        for (int h = 0; h < 8; h++) sm[h] = f2tf(u[h] * inv);
    } else {
        #pragma unroll
        for (int h = 0; h < 8; h++) sm[h] = 0x3e000000u;   // tf32(0.125)
    }
    #pragma unroll
    for (int h = 0; h < 8; h++)
        g_att2[(((size_t)(n * 8 + h)) * 512 + l) * 256 + p] = __uint_as_float(sm[h]);
    int any = __syncthreads_or(valid);
    if (p == 0) g_noedge[n * CL + l] = !any;
}

// -------- unified tf32 MMA kernel: M-tile 64, 4-stage cp.async, 3 CTAs/SM ----
// MODE 0: A=x (cvt at frag), B=g_w1t, +b1, PERM -> g_xh(tf32); fused dots+softmax
// MODE 2: phase1: A=att1 synth (quad layout), B=g_xh -> he0 tile in smem (tf32);
//         phase2: A=sHe, B=g_w3t, +b3 -> g_he(tf32); fused gelu-dot -> g_ae
// MODE 3: per (n,h)x8: A=g_att2, B=g_he, gelu/scatter -> out (fp32)
static const int NSTG = 4;
static const int MT   = 64;          // M-tile rows
static const int SA   = 20;          // A row stride (u32): 16 k + 4 pad (modes 0/3)
static const int ASZ  = MT * SA;     // 1280 words (mode 2 quads use first 1088)
static const int SB   = 136;         // B row stride (u32)
static const int BSZ  = 16 * SB;     // 2176 words
static const int MBW  = MT * 20;     // mbits cache words (MODE 2 only)
// layout (words): sW2 128 | sW4 128 | sD1 256 | sD2 256 | Bs 4*2176 | sS 512 |
//                 As 4*1280 | sMb 1280 (mode2) | sHe overlays As..end (+1792 extra)
static const int BASE_WORDS  = 768 + NSTG * BSZ + 512 + NSTG * ASZ;   // 15104
static const int SMEM_BYTES  = BASE_WORDS * 4;                        // 60416
static const int SMEM2_WORDS = 768 + NSTG * BSZ + 512 + 8192 + 1792;  // As+sMb+extra = sHe 8192
static const int SMEM2_BYTES = (BASE_WORDS + MBW + 1792) * 4;         // 72704

template<int MODE>
__global__ void __launch_bounds__(256, 3) mma_k(const float* __restrict__ Aext,
                                                const float* __restrict__ bias,
                                                const float* __restrict__ wA,
                                                const float* __restrict__ wB,
                                                const float* __restrict__ xin,
                                                float* __restrict__ outx) {
    extern __shared__ unsigned dyns[];
    unsigned* sW2 = dyns;                     // 128
    unsigned* sW4 = sW2 + 128;                // 128
    float* sD1 = (float*)(sW4 + 128);         // 256
    float* sD2 = sD1 + 256;                   // 256
    unsigned* Bs  = (unsigned*)(sD2 + 256);   // NSTG*BSZ
    unsigned* sS  = Bs + NSTG * BSZ;          // 512
    unsigned* As  = sS + 512;                 // NSTG*ASZ
    unsigned* sMb = As + NSTG * ASZ;          // MODE 2: MT*20
    unsigned* sHe = As;                       // MODE 2 phase 2: 8192 words

    const int t = threadIdx.x;

    int nh = 0, m0 = 0, KT = 128, RS = 128;
    const float* Ag = Aext;
    const float* Bg = nullptr;
    if (MODE == 0) { m0 = blockIdx.x * MT; Bg = g_w1t; }
    if (MODE == 2) { nh = blockIdx.x >> 2; m0 = (blockIdx.x & 3) * MT; KT = 512;
                     Bg = g_xh + (size_t)nh * 512 * 128; }
    if (MODE == 3) { nh = blockIdx.x >> 3; m0 = (blockIdx.x & 7) * MT; KT = 256; RS = 256;
                     Ag = g_att2 + (size_t)nh * 512 * 256;
                     Bg = g_he + (size_t)nh * 256 * 128; }
    const int NIT = KT / 16;

    if (MODE == 2) {
        sS[t]       = f2tf(g_s[(size_t)nh * 512 + t]);
        sS[t + 256] = f2tf(g_s[(size_t)nh * 512 + t + 256]);
        if (t < 128) {
            sW2[t] = __float_as_uint(bias[t]);   // b3
            sW4[t] = __float_as_uint(wA[t]);     // W4 lo
        }
        // preload this CTA's mbits slice (MT rows x 16 u32) into smem, stride 20
        {
            int r = t >> 2, q = t & 3;    // 256 chunks of 16B, one per thread
            cpa16(&sMb[r * 20 + q * 4],
                  g_mbits + ((size_t)((nh >> 3) * 256 + m0 + r)) * 16 + q * 4);
        }
        CPA_COMMIT();
        CPA_WAIT0();   // fully drained before the 3 pipeline groups are committed
    } else if (MODE == 0) {
        if (t < 128) {
            sS[t]  = __float_as_uint(bias[t]);
            sW2[t] = __float_as_uint(wA[t]);
            sW4[t] = __float_as_uint(wB[t]);
        }
    }
    __syncthreads();   // sS + sMb visible before synth reads them

    const int lane = t & 31, wid = t >> 5;
    const int gq = lane >> 2, cq = lane & 3;
    const int wm = (wid & 1) * 32, wn = (wid >> 1) * 32;
    const int slotA = (gq * 4 + ((cq + gq) & 3)) * 4;   // MODE 2 quad slot
    const int m16w = wm >> 4;                            // 0 or 2

    float acc[2][4][4];
    #pragma unroll
    for (int a = 0; a < 2; a++)
        #pragma unroll
        for (int b = 0; b < 4; b++)
            #pragma unroll
            for (int c = 0; c < 4; c++) acc[a][b][c] = 0.0f;

    auto issue = [&](int it) {
        if (it < NIT) {
            int k0 = it * 16, st = it & (NSTG - 1);
            #pragma unroll
            for (int rr = 0; rr < 2; rr++) {
                int i = t + 256 * rr;
                cpa16(&Bs[st * BSZ + (i >> 5) * SB + (i & 31) * 4],
                      Bg + (size_t)(k0 + (i >> 5)) * 128 + (i & 31) * 4);
            }
            if (MODE != 2) {
                int row = t >> 2, seg = t & 3;
                cpa16(&As[st * ASZ + row * SA + seg * 4],
                      Ag + (size_t)(m0 + row) * RS + k0 + seg * 4);
            }
        }
        CPA_COMMIT();
    };
    auto synth = [&](int it) {   // MODE 2 only: build one rotated quad per thread
        if (it < NIT) {
            int k0 = it * 16, st = it & (NSTG - 1);
            int b = t >> 5;               // block 0..7: m16 = b>>1, ksc = b&1
            int g = (t >> 2) & 7, c = t & 3;
            int r0 = (b >> 1) * 16 + g;   // row, row+8
            int kc = (b & 1) * 8 + c;     // k within chunk, +4
            int sh = k0 & 16;
            unsigned mb0 = sMb[r0 * 20 + (k0 >> 5)];
            unsigned mb1 = sMb[(r0 + 8) * 20 + (k0 >> 5)];
            unsigned sc  = sS[k0 + kc];
            unsigned sc4 = sS[k0 + kc + 4];
            uint4 q;
            q.x = ((mb0 >> (sh + kc)) & 1u)     ? sc  : 0x3e000000u;
            q.y = ((mb1 >> (sh + kc)) & 1u)     ? sc  : 0x3e000000u;
            q.z = ((mb0 >> (sh + kc + 4)) & 1u) ? sc4 : 0x3e000000u;
            q.w = ((mb1 >> (sh + kc + 4)) & 1u) ? sc4 : 0x3e000000u;
            int slot = (g * 4 + ((c + g) & 3)) * 4;
            *(uint4*)&As[st * ASZ + b * 136 + slot] = q;
        }
    };

    #pragma unroll
    for (int s = 0; s < NSTG - 1; s++) {
        issue(s);
        if (MODE == 2) synth(s);
    }

    for (int it = 0; it < NIT; ++it) {
        CPA_WAIT2();
        __syncthreads();
        const unsigned* Ab = &As[(it & (NSTG - 1)) * ASZ];
        const unsigned* Bb = &Bs[(it & (NSTG - 1)) * BSZ];
        #pragma unroll
        for (int ksc = 0; ksc < 2; ksc++) {
            int ks = ksc * 8;
            unsigned a[2][4], b[4][2];
            #pragma unroll
            for (int mi = 0; mi < 2; mi++) {
                if (MODE == 2) {
                    uint4 v = *(const uint4*)&Ab[((m16w + mi) * 2 + ksc) * 136 + slotA];
                    a[mi][0] = v.x; a[mi][1] = v.y; a[mi][2] = v.z; a[mi][3] = v.w;
                } else {
                    int r0 = (wm + mi * 16 + gq) * SA + ks + cq;
                    a[mi][0] = Ab[r0];
                    a[mi][1] = Ab[r0 + 8 * SA];
                    a[mi][2] = Ab[r0 + 4];
                    a[mi][3] = Ab[r0 + 8 * SA + 4];
                    if (MODE == 0) {
                        a[mi][0] = f2tf(__uint_as_float(a[mi][0]));
                        a[mi][1] = f2tf(__uint_as_float(a[mi][1]));
                        a[mi][2] = f2tf(__uint_as_float(a[mi][2]));
                        a[mi][3] = f2tf(__uint_as_float(a[mi][3]));
                    }
                }
            }
            #pragma unroll
            for (int ni = 0; ni < 4; ni++) {
                int o = (ks + cq) * SB + wn + ni * 8 + gq;
                b[ni][0] = Bb[o];
                b[ni][1] = Bb[o + 4 * SB];
            }
            #pragma unroll
            for (int mi = 0; mi < 2; mi++)
                #pragma unroll
                for (int ni = 0; ni < 4; ni++)
                    mma8(acc[mi][ni], a[mi], b[ni]);
        }
        issue(it + NSTG - 1);
        if (MODE == 2) synth(it + NSTG - 1);
    }

    if (MODE == 2) {
        // ---- phase 1 epilogue: he0 = tf32(gelu(acc)) -> sHe (swizzled) ----
        CPA_WAIT0();
        __syncthreads();   // all phase-1 As/Bs reads done before overwrite
        #pragma unroll
        for (int mi = 0; mi < 2; mi++)
            #pragma unroll
            for (int half = 0; half < 2; half++) {
                int rl = wm + mi * 16 + gq + half * 8;
                #pragma unroll
                for (int ni = 0; ni < 4; ni++) {
                    int col = wn + ni * 8 + 2 * cq;
                    unsigned e0 = f2tf(gelu1(acc[mi][ni][half * 2 + 0]));
                    unsigned e1 = f2tf(gelu1(acc[mi][ni][half * 2 + 1]));
                    int c0 = (col + 4 * rl) & 127;   // even col + even shift: pair safe
                    sHe[rl * 128 + c0]     = e0;
                    sHe[rl * 128 + c0 + 1] = e1;
                }
            }
        __syncthreads();
        // ---- phase 2: he = sHe @ W3 + b3 ----
        #pragma unroll
        for (int a = 0; a < 2; a++)
            #pragma unroll
            for (int b = 0; b < 4; b++)
                #pragma unroll
                for (int c = 0; c < 4; c++) acc[a][b][c] = 0.0f;
        auto issue2 = [&](int it2) {
            if (it2 < 8) {
                int k0 = it2 * 16, st = it2 & 3;
                #pragma unroll
                for (int rr = 0; rr < 2; rr++) {
                    int i = t + 256 * rr;
                    cpa16(&Bs[st * BSZ + (i >> 5) * SB + (i & 31) * 4],
                          g_w3t + (size_t)(k0 + (i >> 5)) * 128 + (i & 31) * 4);
                }
            }
            CPA_COMMIT();
        };
        issue2(0); issue2(1); issue2(2);
        for (int it2 = 0; it2 < 8; ++it2) {
            CPA_WAIT2();
            __syncthreads();
            const unsigned* Bb = &Bs[(it2 & 3) * BSZ];
            #pragma unroll
            for (int ksc = 0; ksc < 2; ksc++) {
                int ks = ksc * 8;
                unsigned a[2][4], b[4][2];
                #pragma unroll
                for (int mi = 0; mi < 2; mi++) {
                    int r0 = wm + mi * 16 + gq;
                    int kk = it2 * 16 + ks + cq;
                    a[mi][0] = sHe[r0 * 128 + ((kk + 4 * r0) & 127)];
                    a[mi][1] = sHe[(r0 + 8) * 128 + ((kk + 4 * (r0 + 8)) & 127)];
                    a[mi][2] = sHe[r0 * 128 + ((kk + 4 + 4 * r0) & 127)];
                    a[mi][3] = sHe[(r0 + 8) * 128 + ((kk + 4 + 4 * (r0 + 8)) & 127)];
                }
                #pragma unroll
                for (int ni = 0; ni < 4; ni++) {
                    int o = (ks + cq) * SB + wn + ni * 8 + gq;
                    b[ni][0] = Bb[o];
                    b[ni][1] = Bb[o + 4 * SB];
                }
                #pragma unroll
                for (int mi = 0; mi < 2; mi++)
                    #pragma unroll
                    for (int ni = 0; ni < 4; ni++)
                        mma8(acc[mi][ni], a[mi], b[ni]);
            }
            issue2(it2 + 3);
            __syncthreads();   // Bs stage consumed before next overwrite lands
        }
        // ---- phase 2 epilogue: +b3, store g_he(tf32), fused gelu-dot -> g_ae ----
        float dA2[4] = {0.0f, 0.0f, 0.0f, 0.0f};
        #pragma unroll
        for (int mi = 0; mi < 2; mi++)
            #pragma unroll
            for (int half = 0; half < 2; half++) {
                int rl = wm + mi * 16 + gq + half * 8;
                int di = mi * 2 + half;
                size_t base = ((size_t)(nh * 256 + m0 + rl)) * 128;
                #pragma unroll
                for (int ni = 0; ni < 4; ni++) {
                    int col = wn + ni * 8 + 2 * cq;
                    float v0 = acc[mi][ni][half * 2 + 0] + __uint_as_float(sW2[col]);
                    float v1 = acc[mi][ni][half * 2 + 1] + __uint_as_float(sW2[col + 1]);
                    float g0 = gelu1(v0), g1 = gelu1(v1);
                    dA2[di] += g0 * __uint_as_float(sW4[col]) + g1 * __uint_as_float(sW4[col + 1]);
                    *(float2*)(g_he + base + col) =
                        make_float2(__uint_as_float(f2tf(v0)), __uint_as_float(f2tf(v1)));
                }
            }
        #pragma unroll
        for (int i = 0; i < 4; i++) {
            dA2[i] += __shfl_xor_sync(0xffffffffu, dA2[i], 1);
            dA2[i] += __shfl_xor_sync(0xffffffffu, dA2[i], 2);
        }
        if (cq == 0) {
            #pragma unroll
            for (int i = 0; i < 4; i++) {
                int rl = wm + (i >> 1) * 16 + gq + 8 * (i & 1);
                sD1[(wid >> 1) * 64 + rl] = dA2[i];
            }
        }
        __syncthreads();
        if (t < 64)
            g_ae[nh * 256 + m0 + t] = sD1[t] + sD1[64 + t] + sD1[128 + t] + sD1[192 + t];
        return;
    }

    // ---------------- epilogue (modes 0, 3) ----------------
    float dA[4], dB[4];
    #pragma unroll
    for (int i = 0; i < 4; i++) { dA[i] = 0.0f; dB[i] = 0.0f; }

    #pragma unroll
    for (int mi = 0; mi < 2; mi++) {
        #pragma unroll
        for (int half = 0; half < 2; half++) {
            int rl = wm + mi * 16 + gq + half * 8;   // 0..63
            int di = mi * 2 + half;
            size_t base = 0;
            int noe = 0;
            if (MODE == 0) {
                int rowg = m0 + rl;
                int n = rowg >> 12, rem = rowg & 4095;
                int l = rem >> 3, h = rem & 7;
                base = ((size_t)((n * 8 + h) * 512 + l)) * 128;
            } else {
                int l = m0 + rl;
                int n = nh >> 3, h = nh & 7;
                noe = g_noedge[n * CL + l];
                base = ((size_t)(n * CL + l)) * 1024 + h * 128;
            }
            #pragma unroll
            for (int ni = 0; ni < 4; ni++) {
                int col = wn + ni * 8 + 2 * cq;
                float v0 = acc[mi][ni][half * 2 + 0];
                float v1 = acc[mi][ni][half * 2 + 1];
                if (MODE == 0) {
                    v0 += __uint_as_float(sS[col]);
                    v1 += __uint_as_float(sS[col + 1]);
                    float g0 = gelu1(v0), g1 = gelu1(v1);
                    dA[di] += g0 * __uint_as_float(sW2[col]) + g1 * __uint_as_float(sW2[col + 1]);
                    dB[di] += g0 * __uint_as_float(sW4[col]) + g1 * __uint_as_float(sW4[col + 1]);
                    *(float2*)(g_xh + base + col) =
                        make_float2(__uint_as_float(f2tf(v0)), __uint_as_float(f2tf(v1)));
                } else {
                    float2 r;
                    if (noe) r = *(const float2*)(xin + base + col);
                    else     r = make_float2(gelu1(v0), gelu1(v1));
                    *(float2*)(outx + base + col) = r;
                }
            }
        }
    }

    if (MODE == 0) {
        #pragma unroll
        for (int i = 0; i < 4; i++) {
            dA[i] += __shfl_xor_sync(0xffffffffu, dA[i], 1);
            dA[i] += __shfl_xor_sync(0xffffffffu, dA[i], 2);
            dB[i] += __shfl_xor_sync(0xffffffffu, dB[i], 1);
            dB[i] += __shfl_xor_sync(0xffffffffu, dB[i], 2);
        }
        if (cq == 0) {
            #pragma unroll
            for (int i = 0; i < 4; i++) {
                int rl = wm + (i >> 1) * 16 + gq + 8 * (i & 1);
                sD1[(wid >> 1) * 64 + rl] = dA[i];
                sD2[(wid >> 1) * 64 + rl] = dB[i];
            }
        }
        __syncthreads();
        if (t < 64) {
            float d1 = sD1[t] + sD1[64 + t] + sD1[128 + t] + sD1[192 + t];
            float d2 = sD2[t] + sD2[64 + t] + sD2[128 + t] + sD2[192 + t];
            int rowg = m0 + t;
            int n = rowg >> 12, rem = rowg & 4095;
            int l = rem >> 3, h = rem & 7;
            g_an[(size_t)(n * 8 + h) * 512 + l] = d2;
            float mx = d1;
            mx = fmaxf(mx, __shfl_xor_sync(0xffffffffu, mx, 1));
            mx = fmaxf(mx, __shfl_xor_sync(0xffffffffu, mx, 2));
            mx = fmaxf(mx, __shfl_xor_sync(0xffffffffu, mx, 4));
            float e = __expf(d1 - mx);
            float se = e;
            se += __shfl_xor_sync(0xffffffffu, se, 1);
            se += __shfl_xor_sync(0xffffffffu, se, 2);
            se += __shfl_xor_sync(0xffffffffu, se, 4);
            g_s[(size_t)(n * 8 + h) * 512 + l] = e / se;
        }
    }
}

extern "C" void kernel_launch(void* const* d_in, const int* in_sizes, int n_in,
                              void* d_out, int out_size) {
    const float* x   = (const float*)d_in[0];
    const float* adj = (const float*)d_in[1];
    const float* W1  = (const float*)d_in[2];
    const float* b1  = (const float*)d_in[3];
    const float* W2  = (const float*)d_in[4];
    const float* W3  = (const float*)d_in[6];
    const float* b3  = (const float*)d_in[7];
    const float* W4  = (const float*)d_in[8];
    float* out = (float*)d_out;
    (void)in_sizes; (void)n_in; (void)out_size;

    cudaFuncSetAttribute(mma_k<0>, cudaFuncAttributeMaxDynamicSharedMemorySize, SMEM_BYTES);
    cudaFuncSetAttribute(mma_k<2>, cudaFuncAttributeMaxDynamicSharedMemorySize, SMEM2_BYTES);
    cudaFuncSetAttribute(mma_k<3>, cudaFuncAttributeMaxDynamicSharedMemorySize, SMEM_BYTES);

    wcvt_k<<<64, 256>>>(W1, W3);
    mbits_k<<<dim3(CL / 32, CN), 256>>>(adj);
    mma_k<0><<<(CN * CL * CH) / MT, 256, SMEM_BYTES>>>(x, b1, W2, W4 + CE, nullptr, nullptr);
    mma_k<2><<<CN * CH * 4, 256, SMEM2_BYTES>>>(nullptr, b3, W4, nullptr, nullptr, nullptr);
    att2fill_k<<<dim3(CL, CN), 256>>>(adj);
    mma_k<3><<<CN * CH * 8, 256, SMEM_BYTES>>>(nullptr, nullptr, nullptr, nullptr, x, out);
}